// round 1
// baseline (speedup 1.0000x reference)
#include <cuda_runtime.h>
#include <math.h>
#include <stdint.h>

// Problem constants (VectorQuantizer: B=8, S=4096, D=512, K=4096)
#define D_DIM 512
#define K_CODES 4096
#define N_MAX 32768
#define COMMIT_F 0.25f

// GEMM tiling
#define BM 128
#define BN 128
#define BK 16

typedef unsigned long long ull;

// ---------------- device scratch (no allocations allowed) ----------------
__device__ ull   g_best[N_MAX];     // packed (sortable-dist << 32) | code index
__device__ float g_cnorm[K_CODES];  // 0.5 * ||c_k||^2
__device__ float g_loss;            // sum of (q - x)^2

// ---------------- helpers ----------------
__device__ __forceinline__ unsigned f2ord(float f) {
    unsigned b = __float_as_uint(f);
    return (b & 0x80000000u) ? ~b : (b | 0x80000000u);
}

// packed fp32x2 FMA (Blackwell-only; ptxas never auto-fuses this)
__device__ __forceinline__ void ffma2(ull& d, ull a, ull b) {
    asm("fma.rn.f32x2 %0, %1, %2, %0;" : "+l"(d) : "l"(a), "l"(b));
}

union F4U { float4 f; ull u[2]; };

// ---------------- init ----------------
__global__ void init_kernel(int N) {
    int i = blockIdx.x * blockDim.x + threadIdx.x;
    if (i < N) g_best[i] = 0xFFFFFFFFFFFFFFFFULL;
    if (i == 0) g_loss = 0.0f;
}

// 0.5 * ||c_k||^2 for every code. One block per code, 128 threads * float4.
__global__ void cnorm_kernel(const float* __restrict__ C) {
    int k = blockIdx.x;
    const float4* row = (const float4*)(C + (size_t)k * D_DIM);
    float4 v = row[threadIdx.x];
    float s = v.x * v.x + v.y * v.y + v.z * v.z + v.w * v.w;
    #pragma unroll
    for (int o = 16; o > 0; o >>= 1) s += __shfl_down_sync(0xffffffffu, s, o);
    __shared__ float ws[4];
    if ((threadIdx.x & 31) == 0) ws[threadIdx.x >> 5] = s;
    __syncthreads();
    if (threadIdx.x == 0) g_cnorm[k] = 0.5f * (ws[0] + ws[1] + ws[2] + ws[3]);
}

// ---------------- distance GEMM + fused argmin ----------------
// score = x . c  (accumulated with packed fp32x2 FMA)
// key   = 0.5*||c||^2 - score ; argmin(key) == argmin of true L2 distance
__global__ __launch_bounds__(256, 2) void dist_kernel(const float* __restrict__ X,
                                                      const float* __restrict__ C) {
    __shared__ __align__(16) float As2[BK][2 * BM + 4];  // A duplicated pairs
    __shared__ __align__(16) float Bs[BK][BN + 4];
    __shared__ ull sbest[BM];

    int tid = threadIdx.x;
    int tx = tid & 15, ty = tid >> 4;
    int rowBase = blockIdx.y * BM;
    int colBase = blockIdx.x * BN;

    if (tid < BM) sbest[tid] = 0xFFFFFFFFFFFFFFFFULL;

    ull acc2[8][4];
    #pragma unroll
    for (int i = 0; i < 8; i++)
        #pragma unroll
        for (int j = 0; j < 4; j++) acc2[i][j] = 0ULL;

    const float* Ab = X + (size_t)rowBase * D_DIM;
    const float* Bb = C + (size_t)colBase * D_DIM;

    for (int k0 = 0; k0 < D_DIM; k0 += BK) {
        #pragma unroll
        for (int q = 0; q < 2; q++) {
            int idx = tid * 2 + q;
            int r = idx >> 2;
            int c4 = (idx & 3) * 4;
            float4 va = *(const float4*)(Ab + (size_t)r * D_DIM + k0 + c4);
            *(float2*)&As2[c4 + 0][2 * r] = make_float2(va.x, va.x);
            *(float2*)&As2[c4 + 1][2 * r] = make_float2(va.y, va.y);
            *(float2*)&As2[c4 + 2][2 * r] = make_float2(va.z, va.z);
            *(float2*)&As2[c4 + 3][2 * r] = make_float2(va.w, va.w);
            float4 vb = *(const float4*)(Bb + (size_t)r * D_DIM + k0 + c4);
            Bs[c4 + 0][r] = vb.x; Bs[c4 + 1][r] = vb.y;
            Bs[c4 + 2][r] = vb.z; Bs[c4 + 3][r] = vb.w;
        }
        __syncthreads();
        #pragma unroll
        for (int k = 0; k < BK; k++) {
            ull a2[8], b2[4];
            #pragma unroll
            for (int ii = 0; ii < 4; ii++) {
                F4U t; t.f = *(const float4*)&As2[k][(ty * 8 + ii * 2) * 2];
                a2[ii * 2] = t.u[0]; a2[ii * 2 + 1] = t.u[1];
            }
            #pragma unroll
            for (int jj = 0; jj < 2; jj++) {
                F4U t; t.f = *(const float4*)&Bs[k][tx * 8 + jj * 4];
                b2[jj * 2] = t.u[0]; b2[jj * 2 + 1] = t.u[1];
            }
            #pragma unroll
            for (int i = 0; i < 8; i++)
                #pragma unroll
                for (int j2 = 0; j2 < 4; j2++)
                    ffma2(acc2[i][j2], a2[i], b2[j2]);
        }
        __syncthreads();
    }

    // per-thread argmin over its 8 codes, then shared/global min-reduce
    #pragma unroll
    for (int i = 0; i < 8; i++) {
        float bv = 3.4e38f;
        int bj = colBase + tx * 8;
        #pragma unroll
        for (int j2 = 0; j2 < 4; j2++) {
            ull v = acc2[i][j2];
            float s0 = __uint_as_float((unsigned)v);
            float s1 = __uint_as_float((unsigned)(v >> 32));
            int c0 = colBase + tx * 8 + j2 * 2;
            float d0 = g_cnorm[c0] - s0;
            float d1 = g_cnorm[c0 + 1] - s1;
            if (d0 < bv) { bv = d0; bj = c0; }
            if (d1 < bv) { bv = d1; bj = c0 + 1; }
        }
        ull key = ((ull)f2ord(bv) << 32) | (unsigned)bj;
        atomicMin(&sbest[ty * 8 + i], key);
    }
    __syncthreads();
    if (tid < BM) atomicMin(&g_best[rowBase + tid], sbest[tid]);
}

// ---------------- gate GEMM + gather + output + loss ----------------
// gate[n,j] = sigmoid( sum_k x[n,k]*W[j,k] + b[j] )
// out = x + codebook[idx] * gate ;  loss_sum += (q - x)^2
__global__ __launch_bounds__(256, 2) void gate_out_kernel(const float* __restrict__ X,
                                                          const float* __restrict__ C,
                                                          const float* __restrict__ W,
                                                          const float* __restrict__ gb,
                                                          float* __restrict__ OUT) {
    __shared__ __align__(16) float As2[BK][2 * BM + 4];
    __shared__ __align__(16) float Bs[BK][BN + 4];

    int tid = threadIdx.x;
    int tx = tid & 15, ty = tid >> 4;
    int rowBase = blockIdx.y * BM;
    int colBase = blockIdx.x * BN;

    ull acc2[8][4];
    #pragma unroll
    for (int i = 0; i < 8; i++)
        #pragma unroll
        for (int j = 0; j < 4; j++) acc2[i][j] = 0ULL;

    const float* Ab = X + (size_t)rowBase * D_DIM;
    const float* Bb = W + (size_t)colBase * D_DIM;

    for (int k0 = 0; k0 < D_DIM; k0 += BK) {
        #pragma unroll
        for (int q = 0; q < 2; q++) {
            int idx = tid * 2 + q;
            int r = idx >> 2;
            int c4 = (idx & 3) * 4;
            float4 va = *(const float4*)(Ab + (size_t)r * D_DIM + k0 + c4);
            *(float2*)&As2[c4 + 0][2 * r] = make_float2(va.x, va.x);
            *(float2*)&As2[c4 + 1][2 * r] = make_float2(va.y, va.y);
            *(float2*)&As2[c4 + 2][2 * r] = make_float2(va.z, va.z);
            *(float2*)&As2[c4 + 3][2 * r] = make_float2(va.w, va.w);
            float4 vb = *(const float4*)(Bb + (size_t)r * D_DIM + k0 + c4);
            Bs[c4 + 0][r] = vb.x; Bs[c4 + 1][r] = vb.y;
            Bs[c4 + 2][r] = vb.z; Bs[c4 + 3][r] = vb.w;
        }
        __syncthreads();
        #pragma unroll
        for (int k = 0; k < BK; k++) {
            ull a2[8], b2[4];
            #pragma unroll
            for (int ii = 0; ii < 4; ii++) {
                F4U t; t.f = *(const float4*)&As2[k][(ty * 8 + ii * 2) * 2];
                a2[ii * 2] = t.u[0]; a2[ii * 2 + 1] = t.u[1];
            }
            #pragma unroll
            for (int jj = 0; jj < 2; jj++) {
                F4U t; t.f = *(const float4*)&Bs[k][tx * 8 + jj * 4];
                b2[jj * 2] = t.u[0]; b2[jj * 2 + 1] = t.u[1];
            }
            #pragma unroll
            for (int i = 0; i < 8; i++)
                #pragma unroll
                for (int j2 = 0; j2 < 4; j2++)
                    ffma2(acc2[i][j2], a2[i], b2[j2]);
        }
        __syncthreads();
    }

    int colb = colBase + tx * 8;
    float bb[8];
    #pragma unroll
    for (int j = 0; j < 8; j++) bb[j] = gb[colb + j];

    float lsum = 0.0f;
    #pragma unroll
    for (int i = 0; i < 8; i++) {
        int row = rowBase + ty * 8 + i;
        unsigned ic = (unsigned)g_best[row];  // low 32 bits = code index
        const float* crow = C + (size_t)ic * D_DIM + colb;
        const float* xrow = X + (size_t)row * D_DIM + colb;
        float* orow = OUT + (size_t)row * D_DIM + colb;

        float4 x0 = *(const float4*)(xrow);
        float4 x1 = *(const float4*)(xrow + 4);
        float4 q0 = *(const float4*)(crow);
        float4 q1 = *(const float4*)(crow + 4);
        float xv[8] = {x0.x, x0.y, x0.z, x0.w, x1.x, x1.y, x1.z, x1.w};
        float qv[8] = {q0.x, q0.y, q0.z, q0.w, q1.x, q1.y, q1.z, q1.w};

        float accf[8];
        #pragma unroll
        for (int j2 = 0; j2 < 4; j2++) {
            ull v = acc2[i][j2];
            accf[2 * j2]     = __uint_as_float((unsigned)v);
            accf[2 * j2 + 1] = __uint_as_float((unsigned)(v >> 32));
        }

        float ov[8];
        #pragma unroll
        for (int j = 0; j < 8; j++) {
            float g = 1.0f / (1.0f + expf(-(accf[j] + bb[j])));
            ov[j] = xv[j] + qv[j] * g;
            float dd = qv[j] - xv[j];
            lsum += dd * dd;
        }
        *(float4*)(orow)     = make_float4(ov[0], ov[1], ov[2], ov[3]);
        *(float4*)(orow + 4) = make_float4(ov[4], ov[5], ov[6], ov[7]);
    }

    // block loss reduction (reuse As2 as scratch; last __syncthreads done above)
    float* red = &As2[0][0];
    red[tid] = lsum;
    __syncthreads();
    #pragma unroll
    for (int s = 128; s > 0; s >>= 1) {
        if (tid < s) red[tid] += red[tid + s];
        __syncthreads();
    }
    if (tid == 0) atomicAdd(&g_loss, red[0]);
}

// ---------------- finalize: write scalar loss after the main output ----------------
__global__ void finalize_kernel(float* __restrict__ OUT, int ND, int out_size) {
    float loss = g_loss * ((1.0f + COMMIT_F) / (float)ND);
    for (int i = ND + (int)threadIdx.x; i < out_size; i += (int)blockDim.x)
        OUT[i] = loss;
}

// ---------------- launch ----------------
extern "C" void kernel_launch(void* const* d_in, const int* in_sizes, int n_in,
                              void* d_out, int out_size) {
    const float* X  = (const float*)d_in[0];  // inputs  [B,S,D]
    const float* C  = (const float*)d_in[1];  // codebook [K,D]
    const float* W  = (const float*)d_in[2];  // gate_w  [D,D]
    const float* gb = (const float*)d_in[3];  // gate_b  [D]
    float* OUT = (float*)d_out;

    int N = in_sizes[0] / D_DIM;  // 32768

    init_kernel<<<(N + 255) / 256, 256>>>(N);
    cnorm_kernel<<<K_CODES, 128>>>(C);
    dist_kernel<<<dim3(K_CODES / BN, N / BM), 256>>>(X, C);
    gate_out_kernel<<<dim3(D_DIM / BN, N / BM), 256>>>(X, C, W, gb, OUT);
    finalize_kernel<<<1, 256>>>(OUT, N * D_DIM, out_size);
}

// round 4
// speedup vs baseline: 5.8118x; 5.8118x over previous
#include <cuda_runtime.h>
#include <cuda_bf16.h>
#include <math.h>
#include <stdint.h>

// Problem constants (VectorQuantizer: B=8, S=4096, D=512, K=4096)
#define D_DIM 512
#define K_CODES 4096
#define N_MAX 32768
#define COMMIT_F 0.25f

typedef unsigned long long ull;
typedef unsigned int u32;

// ---------------- device scratch ----------------
__device__ __nv_bfloat16 g_xbf[N_MAX * D_DIM];    // inputs in bf16 (32MB)
__device__ __nv_bfloat16 g_cbf[K_CODES * D_DIM];  // codebook in bf16 (4MB)
__device__ __nv_bfloat16 g_wbf[D_DIM * D_DIM];    // gate_w in bf16 (512KB)
__device__ float g_cnorm[K_CODES];                // 0.5*||c||^2 (fp32)
__device__ ull   g_best[N_MAX];                   // packed (ordered-dist<<32)|idx
__device__ float g_loss;

// ---------------- PTX helpers (baseline sm_80+ features only) ----------------
__device__ __forceinline__ u32 smem_u32(const void* p) {
    u32 a;
    asm("{ .reg .u64 t; cvta.to.shared.u64 t, %1; cvt.u32.u64 %0, t; }" : "=r"(a) : "l"(p));
    return a;
}
#define CP16(dst, src) asm volatile("cp.async.cg.shared.global [%0], [%1], 16;" :: "r"(dst), "l"(src) : "memory")
#define CP_COMMIT()    asm volatile("cp.async.commit_group;" ::: "memory")
#define CP_WAIT1()     asm volatile("cp.async.wait_group 1;" ::: "memory")
#define CP_WAIT0()     asm volatile("cp.async.wait_group 0;" ::: "memory")

__device__ __forceinline__ void ldsm4(u32* r, u32 addr) {
    asm volatile("ldmatrix.sync.aligned.m8n8.x4.shared.b16 {%0,%1,%2,%3}, [%4];"
                 : "=r"(r[0]), "=r"(r[1]), "=r"(r[2]), "=r"(r[3]) : "r"(addr));
}
__device__ __forceinline__ void mma_bf16(float* c, const u32* a, const u32* b) {
    asm volatile("mma.sync.aligned.m16n8k16.row.col.f32.bf16.bf16.f32 "
                 "{%0,%1,%2,%3}, {%4,%5,%6,%7}, {%8,%9}, {%0,%1,%2,%3};"
                 : "+f"(c[0]), "+f"(c[1]), "+f"(c[2]), "+f"(c[3])
                 : "r"(a[0]), "r"(a[1]), "r"(a[2]), "r"(a[3]), "r"(b[0]), "r"(b[1]));
}
__device__ __forceinline__ unsigned f2ord(float f) {
    unsigned b = __float_as_uint(f);
    return (b & 0x80000000u) ? ~b : (b | 0x80000000u);
}

// ---------------- small kernels ----------------
__global__ void init_kernel(int N) {
    int i = blockIdx.x * blockDim.x + threadIdx.x;
    if (i < N) g_best[i] = 0xFFFFFFFFFFFFFFFFULL;
    if (i == 0) g_loss = 0.0f;
}
__global__ void convert_kernel(const float* __restrict__ S, __nv_bfloat16* __restrict__ Dst) {
    int i = blockIdx.x * blockDim.x + threadIdx.x;   // 4 floats each
    float4 v = ((const float4*)S)[i];
    __nv_bfloat162 a = __floats2bfloat162_rn(v.x, v.y);
    __nv_bfloat162 b = __floats2bfloat162_rn(v.z, v.w);
    ((__nv_bfloat162*)Dst)[i * 2]     = a;
    ((__nv_bfloat162*)Dst)[i * 2 + 1] = b;
}
__global__ void cnorm_kernel(const float* __restrict__ C) {
    int k = blockIdx.x;
    const float4* row = (const float4*)(C + (size_t)k * D_DIM);
    float4 v = row[threadIdx.x];
    float s = v.x * v.x + v.y * v.y + v.z * v.z + v.w * v.w;
    #pragma unroll
    for (int o = 16; o > 0; o >>= 1) s += __shfl_down_sync(0xffffffffu, s, o);
    __shared__ float ws[4];
    if ((threadIdx.x & 31) == 0) ws[threadIdx.x >> 5] = s;
    __syncthreads();
    if (threadIdx.x == 0) g_cnorm[k] = 0.5f * (ws[0] + ws[1] + ws[2] + ws[3]);
}

// ---------------- shared mma.sync mainloop ----------------
// CTA 128x128x512 bf16, 8 warps (2x4), warp tile 64x32, double-buffered cp.async.
// As/Bs: [2][128][40] bf16 (pad 8 -> conflict-free ldmatrix).
#define SROW 40

__device__ __forceinline__ void gemm_mainloop(const __nv_bfloat16* __restrict__ Ag,
                                              const __nv_bfloat16* __restrict__ Bg,
                                              u32 asb, u32 bsb, int tid,
                                              float acc[4][4][4]) {
    int lane = tid & 31, wid = tid >> 5;
    int wm = wid >> 2, wn = wid & 3;

    int r0 = tid >> 1;            // staging: each thread does rows tid/2, 2 segs
    int s0 = (tid & 1) * 2;

    // prefetch tile 0
    #pragma unroll
    for (int q = 0; q < 2; q++) {
        int seg = s0 + q;
        CP16(asb + (u32)((r0 * SROW + seg * 8) * 2), (const char*)(Ag + (size_t)r0 * D_DIM + seg * 8));
        CP16(bsb + (u32)((r0 * SROW + seg * 8) * 2), (const char*)(Bg + (size_t)r0 * D_DIM + seg * 8));
    }
    CP_COMMIT();

    // precompute ldmatrix lane addresses (buffer 0 offsets)
    int am = wm * 64 + (lane & 15);
    int ak = 8 * (lane >> 4);
    int bn = wn * 32 + (lane >> 4) * 8 + (lane & 7);
    int bk = ((lane >> 3) & 1) * 8;

    for (int kt = 0; kt < 16; kt++) {
        int buf = kt & 1;
        if (kt < 15) {
            int nb = buf ^ 1;
            #pragma unroll
            for (int q = 0; q < 2; q++) {
                int seg = s0 + q;
                CP16(asb + (u32)(((nb * 128 + r0) * SROW + seg * 8) * 2),
                     (const char*)(Ag + (size_t)r0 * D_DIM + (kt + 1) * 32 + seg * 8));
                CP16(bsb + (u32)(((nb * 128 + r0) * SROW + seg * 8) * 2),
                     (const char*)(Bg + (size_t)r0 * D_DIM + (kt + 1) * 32 + seg * 8));
            }
            CP_COMMIT();
        }
        CP_WAIT1();
        __syncthreads();

        #pragma unroll
        for (int ks = 0; ks < 2; ks++) {
            u32 af[4][4], bfr[2][4];
            #pragma unroll
            for (int mi = 0; mi < 4; mi++)
                ldsm4(af[mi], asb + (u32)(((buf * 128 + am + mi * 16) * SROW + ks * 16 + ak) * 2));
            #pragma unroll
            for (int p = 0; p < 2; p++)
                ldsm4(bfr[p], bsb + (u32)(((buf * 128 + bn + p * 16) * SROW + ks * 16 + bk) * 2));
            #pragma unroll
            for (int mi = 0; mi < 4; mi++)
                #pragma unroll
                for (int ni = 0; ni < 4; ni++)
                    mma_bf16(acc[mi][ni], af[mi], &bfr[ni >> 1][(ni & 1) * 2]);
        }
        __syncthreads();
    }
    CP_WAIT0();
}

// ---------------- distance GEMM + fused argmin ----------------
__global__ __launch_bounds__(256, 2) void dist_kernel() {
    __shared__ __align__(16) __nv_bfloat16 As[2][128][SROW];
    __shared__ __align__(16) __nv_bfloat16 Bs[2][128][SROW];
    __shared__ ull sbest[128];

    int tid = threadIdx.x;
    int lane = tid & 31, wid = tid >> 5;
    int wm = wid >> 2, wn = wid & 3;
    int rowBase = blockIdx.y * 128;
    int colBase = blockIdx.x * 128;

    if (tid < 128) sbest[tid] = 0xFFFFFFFFFFFFFFFFULL;

    float acc[4][4][4];
    #pragma unroll
    for (int a = 0; a < 4; a++)
        #pragma unroll
        for (int b = 0; b < 4; b++)
            #pragma unroll
            for (int c = 0; c < 4; c++) acc[a][b][c] = 0.0f;

    gemm_mainloop(g_xbf + (size_t)rowBase * D_DIM, g_cbf + (size_t)colBase * D_DIM,
                  smem_u32(&As[0][0][0]), smem_u32(&Bs[0][0][0]), tid, acc);

    // cnorm for this thread's 8 columns
    float cnr[4][2];
    int cq = (lane & 3) * 2;
    #pragma unroll
    for (int ni = 0; ni < 4; ni++) {
        int c0 = colBase + wn * 32 + ni * 8 + cq;
        cnr[ni][0] = g_cnorm[c0];
        cnr[ni][1] = g_cnorm[c0 + 1];
    }
    __syncthreads();

    #pragma unroll
    for (int mi = 0; mi < 4; mi++) {
        #pragma unroll
        for (int h = 0; h < 2; h++) {
            int lr = wm * 64 + mi * 16 + h * 8 + (lane >> 2);
            float bv = 3.4e38f; int bj = 0;
            #pragma unroll
            for (int ni = 0; ni < 4; ni++) {
                #pragma unroll
                for (int c = 0; c < 2; c++) {
                    float d = cnr[ni][c] - acc[mi][ni][h * 2 + c];
                    int j = colBase + wn * 32 + ni * 8 + cq + c;
                    if (d < bv) { bv = d; bj = j; }
                }
            }
            ull key = ((ull)f2ord(bv) << 32) | (unsigned)bj;
            atomicMin(&sbest[lr], key);
        }
    }
    __syncthreads();
    if (tid < 128) atomicMin(&g_best[rowBase + tid], sbest[tid]);
}

// ---------------- gate GEMM + gather + output + loss ----------------
__global__ __launch_bounds__(256, 2) void gate_kernel(const float* __restrict__ X,
                                                      const float* __restrict__ C,
                                                      const float* __restrict__ gb,
                                                      float* __restrict__ OUT) {
    __shared__ __align__(16) __nv_bfloat16 As[2][128][SROW];
    __shared__ __align__(16) __nv_bfloat16 Bs[2][128][SROW];

    int tid = threadIdx.x;
    int lane = tid & 31, wid = tid >> 5;
    int wm = wid >> 2, wn = wid & 3;
    int rowBase = blockIdx.y * 128;
    int colBase = blockIdx.x * 128;

    float acc[4][4][4];
    #pragma unroll
    for (int a = 0; a < 4; a++)
        #pragma unroll
        for (int b = 0; b < 4; b++)
            #pragma unroll
            for (int c = 0; c < 4; c++) acc[a][b][c] = 0.0f;

    gemm_mainloop(g_xbf + (size_t)rowBase * D_DIM, g_wbf + (size_t)colBase * D_DIM,
                  smem_u32(&As[0][0][0]), smem_u32(&Bs[0][0][0]), tid, acc);

    int cq = (lane & 3) * 2;
    float bb[4][2];
    #pragma unroll
    for (int ni = 0; ni < 4; ni++) {
        int c0 = colBase + wn * 32 + ni * 8 + cq;
        bb[ni][0] = gb[c0];
        bb[ni][1] = gb[c0 + 1];
    }

    float lsum = 0.0f;
    #pragma unroll
    for (int mi = 0; mi < 4; mi++) {
        #pragma unroll
        for (int h = 0; h < 2; h++) {
            int row = rowBase + wm * 64 + mi * 16 + h * 8 + (lane >> 2);
            unsigned ic = (unsigned)g_best[row];
            const float* crow = C + (size_t)ic * D_DIM;
            const float* xrow = X + (size_t)row * D_DIM;
            float* orow = OUT + (size_t)row * D_DIM;
            #pragma unroll
            for (int ni = 0; ni < 4; ni++) {
                int c0 = colBase + wn * 32 + ni * 8 + cq;
                float2 xv = *(const float2*)(xrow + c0);
                float2 qv = *(const float2*)(crow + c0);
                float g0 = 1.0f / (1.0f + expf(-(acc[mi][ni][h * 2 + 0] + bb[ni][0])));
                float g1 = 1.0f / (1.0f + expf(-(acc[mi][ni][h * 2 + 1] + bb[ni][1])));
                float2 ov = make_float2(xv.x + qv.x * g0, xv.y + qv.y * g1);
                *(float2*)(orow + c0) = ov;
                float d0 = qv.x - xv.x, d1 = qv.y - xv.y;
                lsum += d0 * d0 + d1 * d1;
            }
        }
    }
    // warp reduce + global atomic
    #pragma unroll
    for (int o = 16; o > 0; o >>= 1) lsum += __shfl_down_sync(0xffffffffu, lsum, o);
    if (lane == 0) atomicAdd(&g_loss, lsum);
}

__global__ void finalize_kernel(float* __restrict__ OUT, int ND, int out_size) {
    float loss = g_loss * ((1.0f + COMMIT_F) / (float)ND);
    for (int i = ND + (int)threadIdx.x; i < out_size; i += (int)blockDim.x)
        OUT[i] = loss;
}

// ---------------- launch ----------------
extern "C" void kernel_launch(void* const* d_in, const int* in_sizes, int n_in,
                              void* d_out, int out_size) {
    const float* X  = (const float*)d_in[0];  // [B,S,D]
    const float* C  = (const float*)d_in[1];  // [K,D]
    const float* W  = (const float*)d_in[2];  // [D,D]
    const float* gb = (const float*)d_in[3];  // [D]
    float* OUT = (float*)d_out;

    int N = in_sizes[0] / D_DIM;  // 32768

    __nv_bfloat16 *xbf, *cbf, *wbf;
    cudaGetSymbolAddress((void**)&xbf, g_xbf);
    cudaGetSymbolAddress((void**)&cbf, g_cbf);
    cudaGetSymbolAddress((void**)&wbf, g_wbf);

    init_kernel<<<(N + 255) / 256, 256>>>(N);
    convert_kernel<<<(N * D_DIM / 4) / 256, 256>>>(X, xbf);
    convert_kernel<<<(K_CODES * D_DIM / 4) / 256, 256>>>(C, cbf);
    convert_kernel<<<(D_DIM * D_DIM / 4) / 256, 256>>>(W, wbf);
    cnorm_kernel<<<K_CODES, 128>>>(C);
    dist_kernel<<<dim3(K_CODES / 128, N / 128), 256>>>();
    gate_kernel<<<dim3(D_DIM / 128, N / 128), 256>>>(X, C, gb, OUT);
    finalize_kernel<<<1, 256>>>(OUT, N * D_DIM, out_size);
}